// round 1
// baseline (speedup 1.0000x reference)
#include <cuda_runtime.h>
#include <cuda_bf16.h>
#include <cstdint>

#define N_NODES 500000
#define N_EDGES 8000000
#define N_ORDERS 4
#define EPO (N_EDGES / N_ORDERS)
#define D 10
#define PD 12   // padded row width (48B, float4-aligned)

// Ping-pong node-state buffers (24MB each) — __device__ globals, no allocation.
__device__ __align__(16) float g_bufA[N_NODES * PD];
__device__ __align__(16) float g_bufB[N_NODES * PD];

// ---------------------------------------------------------------------------
// Vector reductions (sm_90+ vectorized red)
// ---------------------------------------------------------------------------
__device__ __forceinline__ void red_add_v4(float* p, float a, float b, float c, float d) {
    asm volatile("red.global.add.v4.f32 [%0], {%1,%2,%3,%4};"
                 :: "l"(p), "f"(a), "f"(b), "f"(c), "f"(d) : "memory");
}
__device__ __forceinline__ void red_add_v2(float* p, float a, float b) {
    asm volatile("red.global.add.v2.f32 [%0], {%1,%2};"
                 :: "l"(p), "f"(a), "f"(b) : "memory");
}

// ---------------------------------------------------------------------------
// Pad x (N,10) into both ping-pong buffers as (N,12) with zero pad
// ---------------------------------------------------------------------------
__global__ void pad_kernel(const float* __restrict__ x) {
    int node = blockIdx.x * blockDim.x + threadIdx.x;
    if (node >= N_NODES) return;
    const float2* xr = (const float2*)(x + (size_t)node * D);  // 40B rows -> 8B aligned
    float2 r0 = xr[0], r1 = xr[1], r2 = xr[2], r3 = xr[3], r4 = xr[4];
    float4 o0 = make_float4(r0.x, r0.y, r1.x, r1.y);
    float4 o1 = make_float4(r2.x, r2.y, r3.x, r3.y);
    float4 o2 = make_float4(r4.x, r4.y, 0.f, 0.f);
    float4* a = (float4*)(g_bufA + (size_t)node * PD);
    float4* b = (float4*)(g_bufB + (size_t)node * PD);
    a[0] = o0; a[1] = o1; a[2] = o2;
    b[0] = o0; b[1] = o1; b[2] = o2;
}

// ---------------------------------------------------------------------------
// dst = src (float4 copy of full padded state)
// ---------------------------------------------------------------------------
__global__ void copy_kernel(float4* __restrict__ dst, const float4* __restrict__ src) {
    int i = blockIdx.x * blockDim.x + threadIdx.x;
    int n4 = N_NODES * PD / 4;
    if (i < n4) dst[i] = src[i];
}

// ---------------------------------------------------------------------------
// One message-passing step: read xin, atomically accumulate into xout
// (xout was pre-initialized to xin's content).
// msg = (W1-W2) x_i + W2 x_j + w_d * dist + b, scattered to node i.
// ---------------------------------------------------------------------------
__global__ void __launch_bounds__(256)
edge_step_kernel(const float* __restrict__ xin, float* __restrict__ xout,
                 const int* __restrict__ edge_index,
                 const int* __restrict__ orders_row,
                 const float* __restrict__ dist,
                 const float* __restrict__ W_mp,
                 const float* __restrict__ b_mp)
{
    __shared__ __align__(16) float sA[D][PD];   // W1 - W2, zero-padded
    __shared__ __align__(16) float sB[D][PD];   // W2, zero-padded
    __shared__ float swd[D];
    __shared__ float sb[D];

    int tid = threadIdx.x;
    if (tid < D * PD) {
        int c = tid / PD, k = tid % PD;
        float a = 0.f, bb = 0.f;
        if (k < D) {
            float w1 = W_mp[c * 21 + k];
            float w2 = W_mp[c * 21 + 10 + k];
            a = w1 - w2; bb = w2;
        }
        sA[c][k] = a; sB[c][k] = bb;
    }
    if (tid < D) {
        swd[tid] = W_mp[tid * 21 + 20];
        sb[tid]  = b_mp[tid];
    }
    __syncthreads();

    int k = blockIdx.x * blockDim.x + tid;
    if (k >= EPO) return;

    int e = __ldg(orders_row + k);
    int i = __ldg(edge_index + e);
    int j = __ldg(edge_index + N_EDGES + e);
    float dd = __ldg(dist + e);

    const float4* pi = (const float4*)(xin + (size_t)i * PD);
    const float4* pj = (const float4*)(xin + (size_t)j * PD);
    float4 xi0 = pi[0], xi1 = pi[1], xi2 = pi[2];
    float4 xj0 = pj[0], xj1 = pj[1], xj2 = pj[2];

    float acc[D];
#pragma unroll
    for (int c = 0; c < D; c++) {
        const float4* wa = (const float4*)sA[c];
        const float4* wb = (const float4*)sB[c];
        float4 a0 = wa[0], a1 = wa[1], a2 = wa[2];
        float4 b0 = wb[0], b1 = wb[1], b2 = wb[2];
        float s = fmaf(swd[c], dd, sb[c]);
        s = fmaf(a0.x, xi0.x, s); s = fmaf(a0.y, xi0.y, s);
        s = fmaf(a0.z, xi0.z, s); s = fmaf(a0.w, xi0.w, s);
        s = fmaf(a1.x, xi1.x, s); s = fmaf(a1.y, xi1.y, s);
        s = fmaf(a1.z, xi1.z, s); s = fmaf(a1.w, xi1.w, s);
        s = fmaf(a2.x, xi2.x, s); s = fmaf(a2.y, xi2.y, s);
        s = fmaf(b0.x, xj0.x, s); s = fmaf(b0.y, xj0.y, s);
        s = fmaf(b0.z, xj0.z, s); s = fmaf(b0.w, xj0.w, s);
        s = fmaf(b1.x, xj1.x, s); s = fmaf(b1.y, xj1.y, s);
        s = fmaf(b1.z, xj1.z, s); s = fmaf(b1.w, xj1.w, s);
        s = fmaf(b2.x, xj2.x, s); s = fmaf(b2.y, xj2.y, s);
        acc[c] = s;
    }

    float* dst = xout + (size_t)i * PD;
    red_add_v4(dst,     acc[0], acc[1], acc[2], acc[3]);
    red_add_v4(dst + 4, acc[4], acc[5], acc[6], acc[7]);
    red_add_v2(dst + 8, acc[8], acc[9]);
}

// ---------------------------------------------------------------------------
// out[n] = W_out @ x_final[n] + b_out
// ---------------------------------------------------------------------------
__global__ void __launch_bounds__(256)
out_kernel(const float* __restrict__ xin, float* __restrict__ out,
           const float* __restrict__ W_out, const float* __restrict__ b_out)
{
    __shared__ __align__(16) float sW[D][PD];
    __shared__ float sb[D];
    int tid = threadIdx.x;
    if (tid < D * PD) {
        int c = tid / PD, k = tid % PD;
        sW[c][k] = (k < D) ? W_out[c * D + k] : 0.f;
    }
    if (tid < D) sb[tid] = b_out[tid];
    __syncthreads();

    int node = blockIdx.x * blockDim.x + tid;
    if (node >= N_NODES) return;

    const float4* px = (const float4*)(xin + (size_t)node * PD);
    float4 x0 = px[0], x1 = px[1], x2 = px[2];

    float r[D];
#pragma unroll
    for (int c = 0; c < D; c++) {
        const float4* w = (const float4*)sW[c];
        float4 w0 = w[0], w1 = w[1], w2 = w[2];
        float s = sb[c];
        s = fmaf(w0.x, x0.x, s); s = fmaf(w0.y, x0.y, s);
        s = fmaf(w0.z, x0.z, s); s = fmaf(w0.w, x0.w, s);
        s = fmaf(w1.x, x1.x, s); s = fmaf(w1.y, x1.y, s);
        s = fmaf(w1.z, x1.z, s); s = fmaf(w1.w, x1.w, s);
        s = fmaf(w2.x, x2.x, s); s = fmaf(w2.y, x2.y, s);
        r[c] = s;
    }

    float2* o = (float2*)(out + (size_t)node * D);   // 40B rows -> 8B aligned
    o[0] = make_float2(r[0], r[1]);
    o[1] = make_float2(r[2], r[3]);
    o[2] = make_float2(r[4], r[5]);
    o[3] = make_float2(r[6], r[7]);
    o[4] = make_float2(r[8], r[9]);
}

// ---------------------------------------------------------------------------
// Host launcher (graph-capturable: kernels only)
// ---------------------------------------------------------------------------
extern "C" void kernel_launch(void* const* d_in, const int* in_sizes, int n_in,
                              void* d_out, int out_size)
{
    const float* x          = (const float*)d_in[0];
    const int*   edge_index = (const int*)  d_in[1];
    const int*   orders     = (const int*)  d_in[2];
    const float* dist       = (const float*)d_in[3];
    const float* W_mp       = (const float*)d_in[4];
    const float* b_mp       = (const float*)d_in[5];
    const float* W_out      = (const float*)d_in[6];
    const float* b_out      = (const float*)d_in[7];
    float* out = (float*)d_out;

    float* bufA; cudaGetSymbolAddress((void**)&bufA, g_bufA);
    float* bufB; cudaGetSymbolAddress((void**)&bufB, g_bufB);

    const int TB = 256;
    int node_blocks = (N_NODES + TB - 1) / TB;
    int edge_blocks = (EPO + TB - 1) / TB;
    int copy_blocks = (N_NODES * PD / 4 + TB - 1) / TB;

    // bufA = bufB = pad(x)
    pad_kernel<<<node_blocks, TB>>>(x);

    // step 0: read A -> accumulate into B    (B becomes x1)
    edge_step_kernel<<<edge_blocks, TB>>>(bufA, bufB, edge_index, orders + 0 * EPO, dist, W_mp, b_mp);
    copy_kernel<<<copy_blocks, TB>>>((float4*)bufA, (const float4*)bufB);
    // step 1: read B -> accumulate into A    (A becomes x2)
    edge_step_kernel<<<edge_blocks, TB>>>(bufB, bufA, edge_index, orders + 1 * EPO, dist, W_mp, b_mp);
    copy_kernel<<<copy_blocks, TB>>>((float4*)bufB, (const float4*)bufA);
    // step 2: read A -> accumulate into B    (B becomes x3)
    edge_step_kernel<<<edge_blocks, TB>>>(bufA, bufB, edge_index, orders + 2 * EPO, dist, W_mp, b_mp);
    copy_kernel<<<copy_blocks, TB>>>((float4*)bufA, (const float4*)bufB);
    // step 3: read B -> accumulate into A    (A becomes x4 = final)
    edge_step_kernel<<<edge_blocks, TB>>>(bufB, bufA, edge_index, orders + 3 * EPO, dist, W_mp, b_mp);

    out_kernel<<<node_blocks, TB>>>(bufA, out, W_out, b_out);
}

// round 5
// speedup vs baseline: 1.1401x; 1.1401x over previous
#include <cuda_runtime.h>
#include <cuda_bf16.h>
#include <cstdint>

#define N_NODES 500000
#define N_EDGES 8000000
#define N_ORDERS 4
#define EPO (N_EDGES / N_ORDERS)
#define D 10
#define PD 12   // padded row width (48B, float4-aligned)

// Ping-pong node-state buffers (24MB each) + packed edge structs (128MB).
__device__ __align__(16) float g_bufA[N_NODES * PD];
__device__ __align__(16) float g_bufB[N_NODES * PD];
__device__ __align__(16) float4 g_packed[N_EDGES];   // {i, j, dist, pad} bit-cast

// ---------------------------------------------------------------------------
// Vector reductions (sm_90+ vectorized red)
// ---------------------------------------------------------------------------
__device__ __forceinline__ void red_add_v4(float* p, float a, float b, float c, float d) {
    asm volatile("red.global.add.v4.f32 [%0], {%1,%2,%3,%4};"
                 :: "l"(p), "f"(a), "f"(b), "f"(c), "f"(d) : "memory");
}
__device__ __forceinline__ void red_add_v2(float* p, float a, float b) {
    asm volatile("red.global.add.v2.f32 [%0], {%1,%2};"
                 :: "l"(p), "f"(a), "f"(b) : "memory");
}

// ---------------------------------------------------------------------------
// Interleave edge data: g_packed[e] = {i, j, dist[e], 0}  (coalesced R/W)
// ---------------------------------------------------------------------------
__global__ void __launch_bounds__(256)
interleave_kernel(const int* __restrict__ edge_index, const float* __restrict__ dist) {
    int e = blockIdx.x * blockDim.x + threadIdx.x;
    if (e >= N_EDGES) return;
    float4 v;
    v.x = __int_as_float(edge_index[e]);
    v.y = __int_as_float(edge_index[N_EDGES + e]);
    v.z = dist[e];
    v.w = 0.f;
    __stcs(&g_packed[e], v);   // streaming store — don't pollute L2
}

// ---------------------------------------------------------------------------
// Pad x (N,10) into both ping-pong buffers as (N,12) with zero pad
// ---------------------------------------------------------------------------
__global__ void pad_kernel(const float* __restrict__ x) {
    int node = blockIdx.x * blockDim.x + threadIdx.x;
    if (node >= N_NODES) return;
    const float2* xr = (const float2*)(x + (size_t)node * D);
    float2 r0 = xr[0], r1 = xr[1], r2 = xr[2], r3 = xr[3], r4 = xr[4];
    float4 o0 = make_float4(r0.x, r0.y, r1.x, r1.y);
    float4 o1 = make_float4(r2.x, r2.y, r3.x, r3.y);
    float4 o2 = make_float4(r4.x, r4.y, 0.f, 0.f);
    float4* a = (float4*)(g_bufA + (size_t)node * PD);
    float4* b = (float4*)(g_bufB + (size_t)node * PD);
    a[0] = o0; a[1] = o1; a[2] = o2;
    b[0] = o0; b[1] = o1; b[2] = o2;
}

// ---------------------------------------------------------------------------
// dst = src (float4 copy of full padded state)
// ---------------------------------------------------------------------------
__global__ void copy_kernel(float4* __restrict__ dst, const float4* __restrict__ src) {
    int i = blockIdx.x * blockDim.x + threadIdx.x;
    int n4 = N_NODES * PD / 4;
    if (i < n4) dst[i] = src[i];
}

// ---------------------------------------------------------------------------
// One message-passing step: read xin, atomically accumulate into xout
// (xout pre-initialized to xin content).
// msg = (W1-W2) x_i + W2 x_j + w_d*dist + b, scattered to node i.
// ---------------------------------------------------------------------------
__global__ void __launch_bounds__(256, 5)
edge_step_kernel(const float* __restrict__ xin, float* __restrict__ xout,
                 const int* __restrict__ orders_row,
                 const float* __restrict__ W_mp,
                 const float* __restrict__ b_mp)
{
    __shared__ __align__(16) float sA[D][PD];   // W1 - W2, zero-padded
    __shared__ __align__(16) float sB[D][PD];   // W2, zero-padded
    __shared__ float swd[D];
    __shared__ float sb[D];

    int tid = threadIdx.x;
    if (tid < D * PD) {
        int c = tid / PD, k = tid % PD;
        float a = 0.f, bb = 0.f;
        if (k < D) {
            float w1 = W_mp[c * 21 + k];
            float w2 = W_mp[c * 21 + 10 + k];
            a = w1 - w2; bb = w2;
        }
        sA[c][k] = a; sB[c][k] = bb;
    }
    if (tid < D) {
        swd[tid] = W_mp[tid * 21 + 20];
        sb[tid]  = b_mp[tid];
    }
    __syncthreads();

    int k = blockIdx.x * blockDim.x + tid;
    if (k >= EPO) return;

    int e = __ldcs(orders_row + k);                 // streaming (coalesced)
    float4 ed = __ldcs(&g_packed[e]);               // streaming random 16B (one sector)
    int   i  = __float_as_int(ed.x);
    int   j  = __float_as_int(ed.y);
    float dd = ed.z;

    const float4* pi = (const float4*)(xin + (size_t)i * PD);
    const float4* pj = (const float4*)(xin + (size_t)j * PD);
    float4 xi0 = __ldg(pi + 0), xi1 = __ldg(pi + 1), xi2 = __ldg(pi + 2);
    float4 xj0 = __ldg(pj + 0), xj1 = __ldg(pj + 1), xj2 = __ldg(pj + 2);

    float acc[D];
#pragma unroll
    for (int c = 0; c < D; c++) {
        const float4* wa = (const float4*)sA[c];
        const float4* wb = (const float4*)sB[c];
        float4 a0 = wa[0], a1 = wa[1], a2 = wa[2];
        float4 b0 = wb[0], b1 = wb[1], b2 = wb[2];
        float s = fmaf(swd[c], dd, sb[c]);
        s = fmaf(a0.x, xi0.x, s); s = fmaf(a0.y, xi0.y, s);
        s = fmaf(a0.z, xi0.z, s); s = fmaf(a0.w, xi0.w, s);
        s = fmaf(a1.x, xi1.x, s); s = fmaf(a1.y, xi1.y, s);
        s = fmaf(a1.z, xi1.z, s); s = fmaf(a1.w, xi1.w, s);
        s = fmaf(a2.x, xi2.x, s); s = fmaf(a2.y, xi2.y, s);
        s = fmaf(b0.x, xj0.x, s); s = fmaf(b0.y, xj0.y, s);
        s = fmaf(b0.z, xj0.z, s); s = fmaf(b0.w, xj0.w, s);
        s = fmaf(b1.x, xj1.x, s); s = fmaf(b1.y, xj1.y, s);
        s = fmaf(b1.z, xj1.z, s); s = fmaf(b1.w, xj1.w, s);
        s = fmaf(b2.x, xj2.x, s); s = fmaf(b2.y, xj2.y, s);
        acc[c] = s;
    }

    float* dst = xout + (size_t)i * PD;
    red_add_v4(dst,     acc[0], acc[1], acc[2], acc[3]);
    red_add_v4(dst + 4, acc[4], acc[5], acc[6], acc[7]);
    red_add_v2(dst + 8, acc[8], acc[9]);
}

// ---------------------------------------------------------------------------
// out[n] = W_out @ x_final[n] + b_out
// ---------------------------------------------------------------------------
__global__ void __launch_bounds__(256)
out_kernel(const float* __restrict__ xin, float* __restrict__ out,
           const float* __restrict__ W_out, const float* __restrict__ b_out)
{
    __shared__ __align__(16) float sW[D][PD];
    __shared__ float sb[D];
    int tid = threadIdx.x;
    if (tid < D * PD) {
        int c = tid / PD, k = tid % PD;
        sW[c][k] = (k < D) ? W_out[c * D + k] : 0.f;
    }
    if (tid < D) sb[tid] = b_out[tid];
    __syncthreads();

    int node = blockIdx.x * blockDim.x + tid;
    if (node >= N_NODES) return;

    const float4* px = (const float4*)(xin + (size_t)node * PD);
    float4 x0 = px[0], x1 = px[1], x2 = px[2];

    float r[D];
#pragma unroll
    for (int c = 0; c < D; c++) {
        const float4* w = (const float4*)sW[c];
        float4 w0 = w[0], w1 = w[1], w2 = w[2];
        float s = sb[c];
        s = fmaf(w0.x, x0.x, s); s = fmaf(w0.y, x0.y, s);
        s = fmaf(w0.z, x0.z, s); s = fmaf(w0.w, x0.w, s);
        s = fmaf(w1.x, x1.x, s); s = fmaf(w1.y, x1.y, s);
        s = fmaf(w1.z, x1.z, s); s = fmaf(w1.w, x1.w, s);
        s = fmaf(w2.x, x2.x, s); s = fmaf(w2.y, x2.y, s);
        r[c] = s;
    }

    float2* o = (float2*)(out + (size_t)node * D);
    o[0] = make_float2(r[0], r[1]);
    o[1] = make_float2(r[2], r[3]);
    o[2] = make_float2(r[4], r[5]);
    o[3] = make_float2(r[6], r[7]);
    o[4] = make_float2(r[8], r[9]);
}

// ---------------------------------------------------------------------------
// Host launcher (graph-capturable: kernels only)
// ---------------------------------------------------------------------------
extern "C" void kernel_launch(void* const* d_in, const int* in_sizes, int n_in,
                              void* d_out, int out_size)
{
    const float* x          = (const float*)d_in[0];
    const int*   edge_index = (const int*)  d_in[1];
    const int*   orders     = (const int*)  d_in[2];
    const float* dist       = (const float*)d_in[3];
    const float* W_mp       = (const float*)d_in[4];
    const float* b_mp       = (const float*)d_in[5];
    const float* W_out      = (const float*)d_in[6];
    const float* b_out      = (const float*)d_in[7];
    float* out = (float*)d_out;

    float* bufA; cudaGetSymbolAddress((void**)&bufA, g_bufA);
    float* bufB; cudaGetSymbolAddress((void**)&bufB, g_bufB);

    const int TB = 256;
    int node_blocks = (N_NODES + TB - 1) / TB;
    int edge_blocks = (EPO + TB - 1) / TB;
    int copy_blocks = (N_NODES * PD / 4 + TB - 1) / TB;
    int ilv_blocks  = (N_EDGES + TB - 1) / TB;

    interleave_kernel<<<ilv_blocks, TB>>>(edge_index, dist);
    pad_kernel<<<node_blocks, TB>>>(x);

    // step 0: read A -> accumulate into B    (B becomes x1)
    edge_step_kernel<<<edge_blocks, TB>>>(bufA, bufB, orders + 0 * EPO, W_mp, b_mp);
    copy_kernel<<<copy_blocks, TB>>>((float4*)bufA, (const float4*)bufB);
    // step 1: read B -> accumulate into A    (A becomes x2)
    edge_step_kernel<<<edge_blocks, TB>>>(bufB, bufA, orders + 1 * EPO, W_mp, b_mp);
    copy_kernel<<<copy_blocks, TB>>>((float4*)bufB, (const float4*)bufA);
    // step 2: read A -> accumulate into B    (B becomes x3)
    edge_step_kernel<<<edge_blocks, TB>>>(bufA, bufB, orders + 2 * EPO, W_mp, b_mp);
    copy_kernel<<<copy_blocks, TB>>>((float4*)bufA, (const float4*)bufB);
    // step 3: read B -> accumulate into A    (A becomes x4 = final)
    edge_step_kernel<<<edge_blocks, TB>>>(bufB, bufA, orders + 3 * EPO, W_mp, b_mp);

    out_kernel<<<node_blocks, TB>>>(bufA, out, W_out, b_out);
}

// round 6
// speedup vs baseline: 1.1523x; 1.0107x over previous
#include <cuda_runtime.h>
#include <cuda_bf16.h>
#include <cstdint>

#define N_NODES 500000
#define N_EDGES 8000000
#define N_ORDERS 4
#define EPO (N_EDGES / N_ORDERS)
#define D 10
#define PD 12   // padded row width (48B, float4-aligned)

// Device scratch: ping-pong node states (24MB x2), accumulator (24MB),
// per-step {i,j} pairs (64MB), per-step {deg,sumd} (16MB).
__device__ __align__(16) float  g_bufA[N_NODES * PD];
__device__ __align__(16) float  g_bufB[N_NODES * PD];
__device__ __align__(16) float  g_accum[N_NODES * PD];
__device__ __align__(16) int2   g_pairs[N_ORDERS * EPO];
__device__ __align__(16) float2 g_degsd[N_ORDERS * N_NODES];

// ---------------------------------------------------------------------------
// Vector reductions (sm_90+ vectorized red)
// ---------------------------------------------------------------------------
__device__ __forceinline__ void red_add_v4(float* p, float a, float b, float c, float d) {
    asm volatile("red.global.add.v4.f32 [%0], {%1,%2,%3,%4};"
                 :: "l"(p), "f"(a), "f"(b), "f"(c), "f"(d) : "memory");
}
__device__ __forceinline__ void red_add_v2(float* p, float a, float b) {
    asm volatile("red.global.add.v2.f32 [%0], {%1,%2};"
                 :: "l"(p), "f"(a), "f"(b) : "memory");
}

// ---------------------------------------------------------------------------
// Zero the per-step {deg, sumd} arrays (must precede build's atomics)
// ---------------------------------------------------------------------------
__global__ void __launch_bounds__(256)
zero_degsd_kernel() {
    int i = blockIdx.x * blockDim.x + threadIdx.x;
    if (i < N_ORDERS * N_NODES) g_degsd[i] = make_float2(0.f, 0.f);
}

// ---------------------------------------------------------------------------
// Build pass over all 8M order entries:
//   pairs[flat] = {i, j};  degsd[s][i] += {1, dist[e]}
// ---------------------------------------------------------------------------
__global__ void __launch_bounds__(256)
build_kernel(const int* __restrict__ edge_index,
             const int* __restrict__ orders,
             const float* __restrict__ dist)
{
    int flat = blockIdx.x * blockDim.x + threadIdx.x;
    if (flat >= N_ORDERS * EPO) return;
    int s = flat / EPO;
    int e = __ldcs(orders + flat);
    int i = __ldg(edge_index + e);
    int j = __ldg(edge_index + N_EDGES + e);
    float d = __ldg(dist + e);
    __stcs(&g_pairs[flat], make_int2(i, j));
    red_add_v2((float*)&g_degsd[s * N_NODES + i], 1.0f, d);
}

// ---------------------------------------------------------------------------
// Pad x (N,10) -> bufA (N,12), zero-pad; zero accum
// ---------------------------------------------------------------------------
__global__ void __launch_bounds__(256)
pad_kernel(const float* __restrict__ x) {
    int node = blockIdx.x * blockDim.x + threadIdx.x;
    if (node >= N_NODES) return;
    const float2* xr = (const float2*)(x + (size_t)node * D);
    float2 r0 = xr[0], r1 = xr[1], r2 = xr[2], r3 = xr[3], r4 = xr[4];
    float4* a = (float4*)(g_bufA + (size_t)node * PD);
    float4* c = (float4*)(g_accum + (size_t)node * PD);
    a[0] = make_float4(r0.x, r0.y, r1.x, r1.y);
    a[1] = make_float4(r2.x, r2.y, r3.x, r3.y);
    a[2] = make_float4(r4.x, r4.y, 0.f, 0.f);
    float4 z = make_float4(0.f, 0.f, 0.f, 0.f);
    c[0] = z; c[1] = z; c[2] = z;
}

// ---------------------------------------------------------------------------
// Edge pass: accum[i] += x[j]   (raw feature sum; no math)
// ---------------------------------------------------------------------------
__global__ void __launch_bounds__(256)
edge_gather_kernel(const float* __restrict__ xin, const int2* __restrict__ pairs)
{
    int k = blockIdx.x * blockDim.x + threadIdx.x;
    if (k >= EPO) return;
    int2 p = __ldcs(pairs + k);
    const float4* pj = (const float4*)(xin + (size_t)p.y * PD);
    float4 x0 = __ldg(pj + 0), x1 = __ldg(pj + 1), x2 = __ldg(pj + 2);
    float* dst = g_accum + (size_t)p.x * PD;
    red_add_v4(dst,     x0.x, x0.y, x0.z, x0.w);
    red_add_v4(dst + 4, x1.x, x1.y, x1.z, x1.w);
    red_add_v2(dst + 8, x2.x, x2.y);
}

// ---------------------------------------------------------------------------
// Node pass: xout = xin + deg*(A xin + b) + B S + wd*sumd ; accum reset to 0.
// A = W1 - W2, B = W2, wd = last column of W_mp.
// ---------------------------------------------------------------------------
__global__ void __launch_bounds__(256)
node_update_kernel(const float* __restrict__ xin, float* __restrict__ xout,
                   const float2* __restrict__ degsd,
                   const float* __restrict__ W_mp, const float* __restrict__ b_mp)
{
    __shared__ __align__(16) float sA[D][PD];
    __shared__ __align__(16) float sB[D][PD];
    __shared__ float swd[D];
    __shared__ float sb[D];

    int tid = threadIdx.x;
    if (tid < D * PD) {
        int c = tid / PD, k = tid % PD;
        float a = 0.f, bb = 0.f;
        if (k < D) {
            float w1 = W_mp[c * 21 + k];
            float w2 = W_mp[c * 21 + 10 + k];
            a = w1 - w2; bb = w2;
        }
        sA[c][k] = a; sB[c][k] = bb;
    }
    if (tid < D) {
        swd[tid] = W_mp[tid * 21 + 20];
        sb[tid]  = b_mp[tid];
    }
    __syncthreads();

    int node = blockIdx.x * blockDim.x + tid;
    if (node >= N_NODES) return;

    const float4* px = (const float4*)(xin + (size_t)node * PD);
    float4* pacc = (float4*)(g_accum + (size_t)node * PD);
    float4 x0 = px[0], x1 = px[1], x2 = px[2];
    float4 s0 = pacc[0], s1 = pacc[1], s2 = pacc[2];
    float2 ds = __ldg(degsd + node);
    float deg = ds.x, sumd = ds.y;

    float r[D];
#pragma unroll
    for (int c = 0; c < D; c++) {
        const float4* wa = (const float4*)sA[c];
        const float4* wb = (const float4*)sB[c];
        float4 a0 = wa[0], a1 = wa[1], a2 = wa[2];
        float4 b0 = wb[0], b1 = wb[1], b2 = wb[2];
        // t = A x + b
        float t = sb[c];
        t = fmaf(a0.x, x0.x, t); t = fmaf(a0.y, x0.y, t);
        t = fmaf(a0.z, x0.z, t); t = fmaf(a0.w, x0.w, t);
        t = fmaf(a1.x, x1.x, t); t = fmaf(a1.y, x1.y, t);
        t = fmaf(a1.z, x1.z, t); t = fmaf(a1.w, x1.w, t);
        t = fmaf(a2.x, x2.x, t); t = fmaf(a2.y, x2.y, t);
        // u = B S
        float u = 0.f;
        u = fmaf(b0.x, s0.x, u); u = fmaf(b0.y, s0.y, u);
        u = fmaf(b0.z, s0.z, u); u = fmaf(b0.w, s0.w, u);
        u = fmaf(b1.x, s1.x, u); u = fmaf(b1.y, s1.y, u);
        u = fmaf(b1.z, s1.z, u); u = fmaf(b1.w, s1.w, u);
        u = fmaf(b2.x, s2.x, u); u = fmaf(b2.y, s2.y, u);
        float xc = (c < 4) ? ((const float*)&x0)[c] : (c < 8) ? ((const float*)&x1)[c - 4]
                                                              : ((const float*)&x2)[c - 8];
        r[c] = fmaf(deg, t, xc) + u + swd[c] * sumd;
    }

    float4* po = (float4*)(xout + (size_t)node * PD);
    po[0] = make_float4(r[0], r[1], r[2], r[3]);
    po[1] = make_float4(r[4], r[5], r[6], r[7]);
    po[2] = make_float4(r[8], r[9], 0.f, 0.f);
    // reset accumulator for next step
    float4 z = make_float4(0.f, 0.f, 0.f, 0.f);
    pacc[0] = z; pacc[1] = z; pacc[2] = z;
}

// ---------------------------------------------------------------------------
// out[n] = W_out @ x_final[n] + b_out
// ---------------------------------------------------------------------------
__global__ void __launch_bounds__(256)
out_kernel(const float* __restrict__ xin, float* __restrict__ out,
           const float* __restrict__ W_out, const float* __restrict__ b_out)
{
    __shared__ __align__(16) float sW[D][PD];
    __shared__ float sb[D];
    int tid = threadIdx.x;
    if (tid < D * PD) {
        int c = tid / PD, k = tid % PD;
        sW[c][k] = (k < D) ? W_out[c * D + k] : 0.f;
    }
    if (tid < D) sb[tid] = b_out[tid];
    __syncthreads();

    int node = blockIdx.x * blockDim.x + tid;
    if (node >= N_NODES) return;

    const float4* px = (const float4*)(xin + (size_t)node * PD);
    float4 x0 = px[0], x1 = px[1], x2 = px[2];

    float r[D];
#pragma unroll
    for (int c = 0; c < D; c++) {
        const float4* w = (const float4*)sW[c];
        float4 w0 = w[0], w1 = w[1], w2 = w[2];
        float s = sb[c];
        s = fmaf(w0.x, x0.x, s); s = fmaf(w0.y, x0.y, s);
        s = fmaf(w0.z, x0.z, s); s = fmaf(w0.w, x0.w, s);
        s = fmaf(w1.x, x1.x, s); s = fmaf(w1.y, x1.y, s);
        s = fmaf(w1.z, x1.z, s); s = fmaf(w1.w, x1.w, s);
        s = fmaf(w2.x, x2.x, s); s = fmaf(w2.y, x2.y, s);
        r[c] = s;
    }

    float2* o = (float2*)(out + (size_t)node * D);
    o[0] = make_float2(r[0], r[1]);
    o[1] = make_float2(r[2], r[3]);
    o[2] = make_float2(r[4], r[5]);
    o[3] = make_float2(r[6], r[7]);
    o[4] = make_float2(r[8], r[9]);
}

// ---------------------------------------------------------------------------
// Host launcher (graph-capturable: kernels only)
// ---------------------------------------------------------------------------
extern "C" void kernel_launch(void* const* d_in, const int* in_sizes, int n_in,
                              void* d_out, int out_size)
{
    const float* x          = (const float*)d_in[0];
    const int*   edge_index = (const int*)  d_in[1];
    const int*   orders     = (const int*)  d_in[2];
    const float* dist       = (const float*)d_in[3];
    const float* W_mp       = (const float*)d_in[4];
    const float* b_mp       = (const float*)d_in[5];
    const float* W_out      = (const float*)d_in[6];
    const float* b_out      = (const float*)d_in[7];
    float* out = (float*)d_out;

    float*  bufA;  cudaGetSymbolAddress((void**)&bufA,  g_bufA);
    float*  bufB;  cudaGetSymbolAddress((void**)&bufB,  g_bufB);
    int2*   pairs; cudaGetSymbolAddress((void**)&pairs, g_pairs);
    float2* degsd; cudaGetSymbolAddress((void**)&degsd, g_degsd);

    const int TB = 256;
    int node_blocks  = (N_NODES + TB - 1) / TB;
    int edge_blocks  = (EPO + TB - 1) / TB;
    int build_blocks = (N_ORDERS * EPO + TB - 1) / TB;
    int zero_blocks  = (N_ORDERS * N_NODES + TB - 1) / TB;

    // Preprocess (graph-static data): deg/sumd per (step, node) + packed pairs
    zero_degsd_kernel<<<zero_blocks, TB>>>();
    build_kernel<<<build_blocks, TB>>>(edge_index, orders, dist);
    pad_kernel<<<node_blocks, TB>>>(x);

    const float* xc = bufA;  float* xn = bufB;
    for (int s = 0; s < N_ORDERS; s++) {
        edge_gather_kernel<<<edge_blocks, TB>>>(xc, pairs + (size_t)s * EPO);
        node_update_kernel<<<node_blocks, TB>>>(xc, xn, degsd + (size_t)s * N_NODES, W_mp, b_mp);
        const float* t = xc; xc = xn; xn = (float*)t;
    }

    out_kernel<<<node_blocks, TB>>>(xc, out, W_out, b_out);
}

// round 8
// speedup vs baseline: 1.3628x; 1.1827x over previous
#include <cuda_runtime.h>
#include <cuda_bf16.h>
#include <cstdint>

#define N_NODES 500000
#define N_EDGES 8000000
#define N_ORDERS 4
#define EPO (N_EDGES / N_ORDERS)
#define D 10
#define PD 12   // padded row width (48B, float4-aligned)

// Device scratch: ping-pong node states (24MB x2), accumulator (24MB),
// packed edges {i,j,dist,pad} (128MB).
__device__ __align__(16) float  g_bufA[N_NODES * PD];
__device__ __align__(16) float  g_bufB[N_NODES * PD];
__device__ __align__(16) float  g_accum[N_NODES * PD];
__device__ __align__(16) float4 g_packed[N_EDGES];

// ---------------------------------------------------------------------------
// Vector reduction (sm_90+ vectorized red)
// ---------------------------------------------------------------------------
__device__ __forceinline__ void red_add_v4(float* p, float a, float b, float c, float d) {
    asm volatile("red.global.add.v4.f32 [%0], {%1,%2,%3,%4};"
                 :: "l"(p), "f"(a), "f"(b), "f"(c), "f"(d) : "memory");
}

// ---------------------------------------------------------------------------
// Interleave edge data: g_packed[e] = {i, j, dist[e], 0}  (coalesced R/W)
// ---------------------------------------------------------------------------
__global__ void __launch_bounds__(256)
interleave_kernel(const int* __restrict__ edge_index, const float* __restrict__ dist) {
    for (int e = blockIdx.x * blockDim.x + threadIdx.x; e < N_EDGES;
         e += gridDim.x * blockDim.x) {
        float4 v;
        v.x = __int_as_float(edge_index[e]);
        v.y = __int_as_float(edge_index[N_EDGES + e]);
        v.z = dist[e];
        v.w = 0.f;
        __stcs(&g_packed[e], v);   // streaming store — don't pollute L2
    }
}

// ---------------------------------------------------------------------------
// Pad x (N,10) -> bufA (N,12) with zero pad; zero accum row
// ---------------------------------------------------------------------------
__global__ void __launch_bounds__(256)
pad_kernel(const float* __restrict__ x) {
    int node = blockIdx.x * blockDim.x + threadIdx.x;
    if (node >= N_NODES) return;
    const float2* xr = (const float2*)(x + (size_t)node * D);
    float2 r0 = xr[0], r1 = xr[1], r2 = xr[2], r3 = xr[3], r4 = xr[4];
    float4* a = (float4*)(g_bufA + (size_t)node * PD);
    float4* c = (float4*)(g_accum + (size_t)node * PD);
    a[0] = make_float4(r0.x, r0.y, r1.x, r1.y);
    a[1] = make_float4(r2.x, r2.y, r3.x, r3.y);
    a[2] = make_float4(r4.x, r4.y, 0.f, 0.f);
    float4 z = make_float4(0.f, 0.f, 0.f, 0.f);
    c[0] = z; c[1] = z; c[2] = z;
}

// ---------------------------------------------------------------------------
// Edge pass: accum[i] += {x[j], 1, dist}   (deg/sumd ride the third atomic)
// ---------------------------------------------------------------------------
__global__ void __launch_bounds__(256)
edge_gather_kernel(const float* __restrict__ xin, const int* __restrict__ orders_row)
{
    int k = blockIdx.x * blockDim.x + threadIdx.x;
    if (k >= EPO) return;
    int e = __ldcs(orders_row + k);                 // streaming coalesced
    float4 ed = __ldcs(&g_packed[e]);               // streaming random 16B (one sector)
    int   i  = __float_as_int(ed.x);
    int   j  = __float_as_int(ed.y);
    float dd = ed.z;

    const float4* pj = (const float4*)(xin + (size_t)j * PD);
    float4 x0 = __ldg(pj + 0), x1 = __ldg(pj + 1), x2 = __ldg(pj + 2);

    float* dst = g_accum + (size_t)i * PD;
    red_add_v4(dst,     x0.x, x0.y, x0.z, x0.w);
    red_add_v4(dst + 4, x1.x, x1.y, x1.z, x1.w);
    red_add_v4(dst + 8, x2.x, x2.y, 1.0f, dd);      // x8, x9, deg+=1, sumd+=dist
}

// ---------------------------------------------------------------------------
// Node pass: xout = xin + deg*(A xin + b) + B S + wd*sumd ; accum reset to 0.
// A = W1 - W2, B = W2, wd = last column of W_mp. deg/sumd come from accum[10..11].
// ---------------------------------------------------------------------------
__global__ void __launch_bounds__(256)
node_update_kernel(const float* __restrict__ xin, float* __restrict__ xout,
                   const float* __restrict__ W_mp, const float* __restrict__ b_mp)
{
    __shared__ __align__(16) float sA[D][PD];
    __shared__ __align__(16) float sB[D][PD];
    __shared__ float swd[D];
    __shared__ float sb[D];

    int tid = threadIdx.x;
    if (tid < D * PD) {
        int c = tid / PD, k = tid % PD;
        float a = 0.f, bb = 0.f;
        if (k < D) {
            float w1 = W_mp[c * 21 + k];
            float w2 = W_mp[c * 21 + 10 + k];
            a = w1 - w2; bb = w2;
        }
        sA[c][k] = a; sB[c][k] = bb;
    }
    if (tid < D) {
        swd[tid] = W_mp[tid * 21 + 20];
        sb[tid]  = b_mp[tid];
    }
    __syncthreads();

    int node = blockIdx.x * blockDim.x + tid;
    if (node >= N_NODES) return;

    const float4* px = (const float4*)(xin + (size_t)node * PD);
    float4* pacc = (float4*)(g_accum + (size_t)node * PD);
    float4 x0 = px[0], x1 = px[1], x2 = px[2];
    float4 s0 = pacc[0], s1 = pacc[1], s2 = pacc[2];
    float deg = s2.z, sumd = s2.w;

    float r[D];
#pragma unroll
    for (int c = 0; c < D; c++) {
        const float4* wa = (const float4*)sA[c];
        const float4* wb = (const float4*)sB[c];
        float4 a0 = wa[0], a1 = wa[1], a2 = wa[2];
        float4 b0 = wb[0], b1 = wb[1], b2 = wb[2];
        // t = A x + b
        float t = sb[c];
        t = fmaf(a0.x, x0.x, t); t = fmaf(a0.y, x0.y, t);
        t = fmaf(a0.z, x0.z, t); t = fmaf(a0.w, x0.w, t);
        t = fmaf(a1.x, x1.x, t); t = fmaf(a1.y, x1.y, t);
        t = fmaf(a1.z, x1.z, t); t = fmaf(a1.w, x1.w, t);
        t = fmaf(a2.x, x2.x, t); t = fmaf(a2.y, x2.y, t);
        // u = B S (S = sum of x_j)
        float u = 0.f;
        u = fmaf(b0.x, s0.x, u); u = fmaf(b0.y, s0.y, u);
        u = fmaf(b0.z, s0.z, u); u = fmaf(b0.w, s0.w, u);
        u = fmaf(b1.x, s1.x, u); u = fmaf(b1.y, s1.y, u);
        u = fmaf(b1.z, s1.z, u); u = fmaf(b1.w, s1.w, u);
        u = fmaf(b2.x, s2.x, u); u = fmaf(b2.y, s2.y, u);
        float xc = (c < 4) ? ((const float*)&x0)[c] : (c < 8) ? ((const float*)&x1)[c - 4]
                                                              : ((const float*)&x2)[c - 8];
        r[c] = fmaf(deg, t, xc) + u + swd[c] * sumd;
    }

    float4* po = (float4*)(xout + (size_t)node * PD);
    po[0] = make_float4(r[0], r[1], r[2], r[3]);
    po[1] = make_float4(r[4], r[5], r[6], r[7]);
    po[2] = make_float4(r[8], r[9], 0.f, 0.f);
    // reset accumulator for next step
    float4 z = make_float4(0.f, 0.f, 0.f, 0.f);
    pacc[0] = z; pacc[1] = z; pacc[2] = z;
}

// ---------------------------------------------------------------------------
// out[n] = W_out @ x_final[n] + b_out
// ---------------------------------------------------------------------------
__global__ void __launch_bounds__(256)
out_kernel(const float* __restrict__ xin, float* __restrict__ out,
           const float* __restrict__ W_out, const float* __restrict__ b_out)
{
    __shared__ __align__(16) float sW[D][PD];
    __shared__ float sb[D];
    int tid = threadIdx.x;
    if (tid < D * PD) {
        int c = tid / PD, k = tid % PD;
        sW[c][k] = (k < D) ? W_out[c * D + k] : 0.f;
    }
    if (tid < D) sb[tid] = b_out[tid];
    __syncthreads();

    int node = blockIdx.x * blockDim.x + tid;
    if (node >= N_NODES) return;

    const float4* px = (const float4*)(xin + (size_t)node * PD);
    float4 x0 = px[0], x1 = px[1], x2 = px[2];

    float r[D];
#pragma unroll
    for (int c = 0; c < D; c++) {
        const float4* w = (const float4*)sW[c];
        float4 w0 = w[0], w1 = w[1], w2 = w[2];
        float s = sb[c];
        s = fmaf(w0.x, x0.x, s); s = fmaf(w0.y, x0.y, s);
        s = fmaf(w0.z, x0.z, s); s = fmaf(w0.w, x0.w, s);
        s = fmaf(w1.x, x1.x, s); s = fmaf(w1.y, x1.y, s);
        s = fmaf(w1.z, x1.z, s); s = fmaf(w1.w, x1.w, s);
        s = fmaf(w2.x, x2.x, s); s = fmaf(w2.y, x2.y, s);
        r[c] = s;
    }

    float2* o = (float2*)(out + (size_t)node * D);
    o[0] = make_float2(r[0], r[1]);
    o[1] = make_float2(r[2], r[3]);
    o[2] = make_float2(r[4], r[5]);
    o[3] = make_float2(r[6], r[7]);
    o[4] = make_float2(r[8], r[9]);
}

// ---------------------------------------------------------------------------
// Host launcher (graph-capturable: kernels only)
// ---------------------------------------------------------------------------
extern "C" void kernel_launch(void* const* d_in, const int* in_sizes, int n_in,
                              void* d_out, int out_size)
{
    const float* x          = (const float*)d_in[0];
    const int*   edge_index = (const int*)  d_in[1];
    const int*   orders     = (const int*)  d_in[2];
    const float* dist       = (const float*)d_in[3];
    const float* W_mp       = (const float*)d_in[4];
    const float* b_mp       = (const float*)d_in[5];
    const float* W_out      = (const float*)d_in[6];
    const float* b_out      = (const float*)d_in[7];
    float* out = (float*)d_out;

    float* bufA; cudaGetSymbolAddress((void**)&bufA, g_bufA);
    float* bufB; cudaGetSymbolAddress((void**)&bufB, g_bufB);

    const int TB = 256;
    int node_blocks = (N_NODES + TB - 1) / TB;
    int edge_blocks = (EPO + TB - 1) / TB;
    int ilv_blocks  = 4736;   // grid-stride; ~32 CTAs/SM wave pattern

    interleave_kernel<<<ilv_blocks, TB>>>(edge_index, dist);
    pad_kernel<<<node_blocks, TB>>>(x);

    const float* xc = bufA;  float* xn = bufB;
    for (int s = 0; s < N_ORDERS; s++) {
        edge_gather_kernel<<<edge_blocks, TB>>>(xc, orders + (size_t)s * EPO);
        node_update_kernel<<<node_blocks, TB>>>(xc, xn, W_mp, b_mp);
        const float* t = xc; xc = xn; xn = (float*)t;
    }

    out_kernel<<<node_blocks, TB>>>(xc, out, W_out, b_out);
}